// round 16
// baseline (speedup 1.0000x reference)
#include <cuda_runtime.h>
#include <cuda_bf16.h>
#include <cstdint>

#define TILE    64
#define THREADS 128
#define GRID    296              // 2 CTAs per SM x 148
#define STRIDE_E 136             // bf16 elems per padded row
#define STRIDE_B 272             // bytes per padded row

// SMEM byte offsets
#define W2HI_OFF 0               // W2 [k][n] hi  128x136 bf16 = 34816B
#define W2LO_OFF 34816
#define H1HI_OFF 69632           // h1 [m][k] hi  64x136 bf16 = 17408B
#define H1LO_OFF 87040
#define SMALL_OFF 104448         // floats: sW1 640|sb1 128|sb2 128|sW3T 384|sb3 4|spart 192
#define SMEM_TOTAL (104448 + 5904)

__device__ __forceinline__ uint32_t smem_u32(const void* p) {
    uint32_t a;
    asm("{ .reg .u64 t; cvta.to.shared.u64 t, %1; cvt.u32.u64 %0, t; }"
        : "=r"(a) : "l"(p));
    return a;
}

__device__ __forceinline__ void ldsm4(uint32_t* r, uint32_t addr) {
    asm volatile("ldmatrix.sync.aligned.m8n8.x4.shared.b16 {%0,%1,%2,%3}, [%4];"
                 : "=r"(r[0]), "=r"(r[1]), "=r"(r[2]), "=r"(r[3]) : "r"(addr));
}
__device__ __forceinline__ void ldsm4t(uint32_t* r, uint32_t addr) {
    asm volatile("ldmatrix.sync.aligned.m8n8.x4.trans.shared.b16 {%0,%1,%2,%3}, [%4];"
                 : "=r"(r[0]), "=r"(r[1]), "=r"(r[2]), "=r"(r[3]) : "r"(addr));
}
__device__ __forceinline__ void mma16816(float* d, const uint32_t* a,
                                         uint32_t b0, uint32_t b1) {
    asm volatile("mma.sync.aligned.m16n8k16.row.col.f32.bf16.bf16.f32 "
                 "{%0,%1,%2,%3}, {%4,%5,%6,%7}, {%8,%9}, {%0,%1,%2,%3};"
                 : "+f"(d[0]), "+f"(d[1]), "+f"(d[2]), "+f"(d[3])
                 : "r"(a[0]), "r"(a[1]), "r"(a[2]), "r"(a[3]), "r"(b0), "r"(b1));
}

#define FMA_F32X2(d, a, b, c) \
    asm("fma.rn.f32x2 %0, %1, %2, %3;" : "=l"(d) : "l"(a), "l"(b), "l"(c))
#define PACK_F32X2(out, lo, hi) \
    asm("mov.b64 %0, {%1, %2};" : "=l"(out) : "f"(lo), "f"(hi))
#define UNPACK_F32X2(lo, hi, in) \
    asm("mov.b64 {%0, %1}, %2;" : "=f"(lo), "=f"(hi) : "l"(in))

__global__ __launch_bounds__(THREADS)
void dyn_reward_hmma_kernel(const float* __restrict__ s, const float* __restrict__ a,
                            const float* __restrict__ W1, const float* __restrict__ b1,
                            const float* __restrict__ W2, const float* __restrict__ b2,
                            const float* __restrict__ W3, const float* __restrict__ b3,
                            float* __restrict__ out, int B, int ntile) {
    extern __shared__ char sm[];
    const uint32_t smbase = smem_u32(sm);

    float* smallf = (float*)(sm + SMALL_OFF);
    float* sW1   = smallf;           // 640
    float* sb1   = sW1 + 640;        // 128
    float* sb2   = sb1 + 128;        // 128
    float* sW3T  = sb2 + 128;        // 384 : sW3T[t*128+j] = W3[j][t]
    float* sb3   = sW3T + 384;       // 4
    float* spart = sb3 + 4;          // 192 : partial layer3 sums, col-half 1

    const int tid = threadIdx.x;
    const int w = tid >> 5, lane = tid & 31;
    const int rg = w & 1;            // row group (32 rows)
    const int ch = w >> 1;           // column half (64 cols)
    const int bid = blockIdx.x;

    // ---------------- one-time staging ----------------
    for (int i = tid; i < 640; i += THREADS) sW1[i] = W1[i];
    for (int i = tid; i < 384; i += THREADS) {
        int tt = i >> 7, j = i & 127;
        sW3T[i] = W3[j * 3 + tt];
    }
    if (tid < 128) { sb1[tid] = b1[tid]; sb2[tid] = b2[tid]; }
    if (tid < 3)   { sb3[tid] = b3[tid]; }
    {
        __nv_bfloat16* w2h = (__nv_bfloat16*)(sm + W2HI_OFF);
        __nv_bfloat16* w2l = (__nv_bfloat16*)(sm + W2LO_OFF);
        for (int idx = tid; idx < 16384; idx += THREADS) {
            int k = idx >> 7, n = idx & 127;
            float wv = W2[idx];
            __nv_bfloat16 hi = __float2bfloat16_rn(wv);
            __nv_bfloat16 lo = __float2bfloat16_rn(wv - __bfloat162float(hi));
            w2h[k * STRIDE_E + n] = hi;
            w2l[k * STRIDE_E + n] = lo;
        }
    }
    __syncthreads();

    // ldmatrix lane-address offsets; two 16-row subtiles per warp
    const uint32_t a_off0 = (uint32_t)((rg * 32 +      (lane & 15)) * STRIDE_B + ((lane >> 4) << 4));
    const uint32_t a_off1 = (uint32_t)((rg * 32 + 16 + (lane & 15)) * STRIDE_B + ((lane >> 4) << 4));
    const uint32_t b_off  = (uint32_t)((lane & 15) * STRIDE_B + ((lane >> 4) << 4) + ch * 128);

    // -------- one-time: cache ALL Bhi fragments in registers (128 regs) -----
    uint32_t bhi[8][4][4];
    {
        const uint32_t BbHi = smbase + W2HI_OFF + b_off;
        #pragma unroll
        for (int ks = 0; ks < 8; ++ks)
            #pragma unroll
            for (int p = 0; p < 4; ++p)
                ldsm4t(bhi[ks][p], BbHi + (uint32_t)(ks * 16 * STRIDE_B + p * 32));
    }

    const int nt = (ntile - bid + GRID - 1) / GRID;

    for (int it = 0; it < nt; ++it) {
        const int R0 = (bid + it * GRID) * TILE;

        // ---- layer 1: h1 = relu(xW1+b1), packed f32x2 FMA, split hi/lo ----
        {
            const int row = tid & 63;
            const int half = tid >> 6;         // 0..1 -> 64 features each
            const int R = R0 + row;
            const float x0 = s[(size_t)R * 3 + 0];
            const float x1 = s[(size_t)R * 3 + 1];
            const float x2 = s[(size_t)R * 3 + 2];
            const float x3 = a[(size_t)R * 2 + 0];
            const float x4 = a[(size_t)R * 2 + 1];
            unsigned long long xp0, xp1, xp2, xp3, xp4;
            PACK_F32X2(xp0, x0, x0);
            PACK_F32X2(xp1, x1, x1);
            PACK_F32X2(xp2, x2, x2);
            PACK_F32X2(xp3, x3, x3);
            PACK_F32X2(xp4, x4, x4);
            char* hiP = sm + H1HI_OFF;
            char* loP = sm + H1LO_OFF;
            #pragma unroll
            for (int g = 0; g < 8; ++g) {
                const int j = half * 64 + g * 8;
                // packed accumulators: vv[q] covers features (j+2q, j+2q+1)
                unsigned long long vv[4];
                {
                    const ulonglong2 bpa = *(const ulonglong2*)(sb1 + j);
                    const ulonglong2 bpb = *(const ulonglong2*)(sb1 + j + 4);
                    vv[0] = bpa.x; vv[1] = bpa.y; vv[2] = bpb.x; vv[3] = bpb.y;
                }
                #pragma unroll
                for (int i5 = 0; i5 < 5; ++i5) {
                    const unsigned long long xp =
                        (i5 == 0) ? xp0 : (i5 == 1) ? xp1 : (i5 == 2) ? xp2
                        : (i5 == 3) ? xp3 : xp4;
                    const ulonglong2 wpa = *(const ulonglong2*)(sW1 + i5 * 128 + j);
                    const ulonglong2 wpb = *(const ulonglong2*)(sW1 + i5 * 128 + j + 4);
                    FMA_F32X2(vv[0], xp, wpa.x, vv[0]);
                    FMA_F32X2(vv[1], xp, wpa.y, vv[1]);
                    FMA_F32X2(vv[2], xp, wpb.x, vv[2]);
                    FMA_F32X2(vv[3], xp, wpb.y, vv[3]);
                }
                uint32_t hw[4], lw[4];
                #pragma unroll
                for (int q = 0; q < 4; ++q) {
                    float va, vb;
                    UNPACK_F32X2(va, vb, vv[q]);
                    float2 vvf = make_float2(fmaxf(va, 0.0f), fmaxf(vb, 0.0f));
                    __nv_bfloat162 hp = __float22bfloat162_rn(vvf);
                    float2 hf = __bfloat1622float2(hp);
                    float2 rv = make_float2(vvf.x - hf.x, vvf.y - hf.y);
                    __nv_bfloat162 lp = __float22bfloat162_rn(rv);
                    hw[q] = *reinterpret_cast<uint32_t*>(&hp);
                    lw[q] = *reinterpret_cast<uint32_t*>(&lp);
                }
                const uint32_t off = (uint32_t)(row * STRIDE_B + j * 2);
                *reinterpret_cast<uint4*>(hiP + off) = make_uint4(hw[0], hw[1], hw[2], hw[3]);
                *reinterpret_cast<uint4*>(loP + off) = make_uint4(lw[0], lw[1], lw[2], lw[3]);
            }
        }
        __syncthreads();

        // ------- layer 2: 3-pass bf16x3 HMMA, warp = 32 rows x 64 cols --
        // (byte-identical structure to the R10 kernel — do not perturb)
        float acc0[32], acc1[32];
        #pragma unroll
        for (int z = 0; z < 32; ++z) { acc0[z] = 0.0f; acc1[z] = 0.0f; }

        // pass 0: Ahi * Bhi  (B from registers)
        {
            const uint32_t Ab0 = smbase + H1HI_OFF + a_off0;
            const uint32_t Ab1 = smbase + H1HI_OFF + a_off1;
            #pragma unroll
            for (int ks = 0; ks < 8; ++ks) {
                uint32_t af0[4], af1[4];
                ldsm4(af0, Ab0 + ks * 32);
                ldsm4(af1, Ab1 + ks * 32);
                #pragma unroll
                for (int p = 0; p < 4; ++p) {
                    mma16816(acc0 + (p * 2 + 0) * 4, af0, bhi[ks][p][0], bhi[ks][p][1]);
                    mma16816(acc0 + (p * 2 + 1) * 4, af0, bhi[ks][p][2], bhi[ks][p][3]);
                    mma16816(acc1 + (p * 2 + 0) * 4, af1, bhi[ks][p][0], bhi[ks][p][1]);
                    mma16816(acc1 + (p * 2 + 1) * 4, af1, bhi[ks][p][2], bhi[ks][p][3]);
                }
            }
        }
        // pass 1: Ahi * Blo  (B from SMEM)
        {
            const uint32_t Ab0 = smbase + H1HI_OFF + a_off0;
            const uint32_t Ab1 = smbase + H1HI_OFF + a_off1;
            const uint32_t Bb  = smbase + W2LO_OFF + b_off;
            #pragma unroll
            for (int ks = 0; ks < 8; ++ks) {
                uint32_t af0[4], af1[4], bfr[4][4];
                ldsm4(af0, Ab0 + ks * 32);
                ldsm4(af1, Ab1 + ks * 32);
                #pragma unroll
                for (int p = 0; p < 4; ++p)
                    ldsm4t(bfr[p], Bb + (uint32_t)(ks * 16 * STRIDE_B + p * 32));
                #pragma unroll
                for (int p = 0; p < 4; ++p) {
                    mma16816(acc0 + (p * 2 + 0) * 4, af0, bfr[p][0], bfr[p][1]);
                    mma16816(acc0 + (p * 2 + 1) * 4, af0, bfr[p][2], bfr[p][3]);
                    mma16816(acc1 + (p * 2 + 0) * 4, af1, bfr[p][0], bfr[p][1]);
                    mma16816(acc1 + (p * 2 + 1) * 4, af1, bfr[p][2], bfr[p][3]);
                }
            }
        }
        // pass 2: Alo * Bhi  (B from registers)
        {
            const uint32_t Ab0 = smbase + H1LO_OFF + a_off0;
            const uint32_t Ab1 = smbase + H1LO_OFF + a_off1;
            #pragma unroll
            for (int ks = 0; ks < 8; ++ks) {
                uint32_t af0[4], af1[4];
                ldsm4(af0, Ab0 + ks * 32);
                ldsm4(af1, Ab1 + ks * 32);
                #pragma unroll
                for (int p = 0; p < 4; ++p) {
                    mma16816(acc0 + (p * 2 + 0) * 4, af0, bhi[ks][p][0], bhi[ks][p][1]);
                    mma16816(acc0 + (p * 2 + 1) * 4, af0, bhi[ks][p][2], bhi[ks][p][3]);
                    mma16816(acc1 + (p * 2 + 0) * 4, af1, bhi[ks][p][0], bhi[ks][p][1]);
                    mma16816(acc1 + (p * 2 + 1) * 4, af1, bhi[ks][p][2], bhi[ks][p][3]);
                }
            }
        }

        // ------- layer 3 partials over this warp's 64 cols (4 rows/lane)
        float po[4][3];
        #pragma unroll
        for (int z = 0; z < 4; ++z) po[z][0] = po[z][1] = po[z][2] = 0.0f;

        #pragma unroll
        for (int t = 0; t < 2; ++t) {
            const float* acc = t ? acc1 : acc0;
            #pragma unroll
            for (int ntl = 0; ntl < 8; ++ntl) {
                const int c0 = ch * 64 + ntl * 8 + (lane & 3) * 2;
                const float2 b2v = *(const float2*)(sb2 + c0);
                const float2 wav = *(const float2*)(sW3T + c0);
                const float2 wbv = *(const float2*)(sW3T + 128 + c0);
                const float2 wcv = *(const float2*)(sW3T + 256 + c0);
                const float h00 = fmaxf(acc[ntl*4+0] + b2v.x, 0.0f);
                const float h01 = fmaxf(acc[ntl*4+1] + b2v.y, 0.0f);
                const float h10 = fmaxf(acc[ntl*4+2] + b2v.x, 0.0f);
                const float h11 = fmaxf(acc[ntl*4+3] + b2v.y, 0.0f);
                po[t*2+0][0] = fmaf(h00, wav.x, fmaf(h01, wav.y, po[t*2+0][0]));
                po[t*2+0][1] = fmaf(h00, wbv.x, fmaf(h01, wbv.y, po[t*2+0][1]));
                po[t*2+0][2] = fmaf(h00, wcv.x, fmaf(h01, wcv.y, po[t*2+0][2]));
                po[t*2+1][0] = fmaf(h10, wav.x, fmaf(h11, wav.y, po[t*2+1][0]));
                po[t*2+1][1] = fmaf(h10, wbv.x, fmaf(h11, wbv.y, po[t*2+1][1]));
                po[t*2+1][2] = fmaf(h10, wcv.x, fmaf(h11, wcv.y, po[t*2+1][2]));
            }
        }
        #pragma unroll
        for (int d = 1; d < 4; d <<= 1) {
            #pragma unroll
            for (int z = 0; z < 4; ++z) {
                po[z][0] += __shfl_xor_sync(0xFFFFFFFFu, po[z][0], d);
                po[z][1] += __shfl_xor_sync(0xFFFFFFFFu, po[z][1], d);
                po[z][2] += __shfl_xor_sync(0xFFFFFFFFu, po[z][2], d);
            }
        }
        // rows for z = t*2+rr : rg*32 + t*16 + rr*8 + (lane>>2)
        if (ch == 1 && (lane & 3) == 0) {
            #pragma unroll
            for (int z = 0; z < 4; ++z) {
                const int lr = rg * 32 + (z >> 1) * 16 + (z & 1) * 8 + (lane >> 2);
                spart[lr * 3 + 0] = po[z][0];
                spart[lr * 3 + 1] = po[z][1];
                spart[lr * 3 + 2] = po[z][2];
            }
        }
        __syncthreads();    // spart ready AND h1 LDSM complete (reusable next tile)

        if (ch == 0 && (lane & 3) == 0) {
            #pragma unroll
            for (int z = 0; z < 4; ++z) {
                const int lr = rg * 32 + (z >> 1) * 16 + (z & 1) * 8 + (lane >> 2);
                const int R = R0 + lr;
                out[(size_t)R * 3 + 0] = po[z][0] + spart[lr * 3 + 0] + sb3[0];
                out[(size_t)R * 3 + 1] = po[z][1] + spart[lr * 3 + 1] + sb3[1];
                out[(size_t)R * 3 + 2] = po[z][2] + spart[lr * 3 + 2] + sb3[2];
            }
        }
        // ---- reward: ch0 warps, ONE row per lane (parallel, coalesced) ----
        if (ch == 0) {
            const int R = R0 + rg * 32 + lane;
            const float x0 = s[(size_t)R * 3 + 0];
            const float x1 = s[(size_t)R * 3 + 1];
            const float x3 = a[(size_t)R * 2 + 0];
            const float x4 = a[(size_t)R * 2 + 1];
            const float INV2VAR = 14.2857142857f;
            const float GC      = 454.728409f;
            const float BEXP    = 555.5555556f;
            const float BC      = 132.9807601f;
            float g = 0.0f, dx, dy, t;
            dx = x0;        dy = x1;        g += __expf(-(dx*dx + dy*dy) * INV2VAR);
            dx = x0;        dy = x1 - 0.2f; g += __expf(-(dx*dx + dy*dy) * INV2VAR);
            dx = x0;        dy = x1 - 0.4f; g += __expf(-(dx*dx + dy*dy) * INV2VAR);
            dx = x0;        dy = x1 - 0.6f; g += __expf(-(dx*dx + dy*dy) * INV2VAR);
            dx = x0;        dy = x1 - 0.8f; g += __expf(-(dx*dx + dy*dy) * INV2VAR);
            dx = x0 + 0.8f; dy = x1 + 0.8f; g += __expf(-(dx*dx + dy*dy) * INV2VAR);
            const float dq0 = x0 - x3, dq1 = x1 - x4;
            const float quad = 30.0f * (dq0 * dq0 + dq1 * dq1);
            float bs = 0.0f;
            t = x0 + 1.5f; bs += __expf(-t * t * BEXP);
            t = x0 - 1.5f; bs += __expf(-t * t * BEXP);
            t = x1 - 1.0f; bs += __expf(-t * t * BEXP);
            t = x1 + 1.0f; bs += __expf(-t * t * BEXP);
            out[(size_t)B * 3 + R] = -(quad + GC * g + BC * bs);
        }
    }
}

extern "C" void kernel_launch(void* const* d_in, const int* in_sizes, int n_in,
                              void* d_out, int out_size) {
    const float* s  = (const float*)d_in[0];
    const float* a  = (const float*)d_in[1];
    const float* W1 = (const float*)d_in[2];
    const float* b1 = (const float*)d_in[3];
    const float* W2 = (const float*)d_in[4];
    const float* b2 = (const float*)d_in[5];
    const float* W3 = (const float*)d_in[6];
    const float* b3 = (const float*)d_in[7];
    float* out = (float*)d_out;

    const int B = in_sizes[0] / 3;
    const int ntile = B / TILE;       // 8192
    cudaFuncSetAttribute(dyn_reward_hmma_kernel,
                         cudaFuncAttributeMaxDynamicSharedMemorySize, SMEM_TOTAL);
    const int grid = (ntile < GRID) ? ntile : GRID;
    dyn_reward_hmma_kernel<<<grid, THREADS, SMEM_TOTAL>>>(s, a, W1, b1, W2, b2, W3, b3,
                                                          out, B, ntile);
}

// round 17
// speedup vs baseline: 1.0153x; 1.0153x over previous
#include <cuda_runtime.h>
#include <cuda_bf16.h>
#include <cstdint>

#define TILE    64
#define THREADS 128
#define GRID    296              // 2 CTAs per SM x 148
#define STRIDE_E 136             // bf16 elems per padded row
#define STRIDE_B 272             // bytes per padded row

// SMEM byte offsets
#define W2HI_OFF 0               // W2 [k][n] hi  128x136 bf16 = 34816B
#define W2LO_OFF 34816
#define H1HI_OFF 69632           // h1 [m][k] hi  64x136 bf16 = 17408B
#define H1LO_OFF 87040
#define SMALL_OFF 104448         // floats: sW1 640|sb1 128|sb2 128|sW3T 384|sb3 4|spart 192
#define SMEM_TOTAL (104448 + 5904)

__device__ __forceinline__ uint32_t smem_u32(const void* p) {
    uint32_t a;
    asm("{ .reg .u64 t; cvta.to.shared.u64 t, %1; cvt.u32.u64 %0, t; }"
        : "=r"(a) : "l"(p));
    return a;
}

__device__ __forceinline__ void ldsm4(uint32_t* r, uint32_t addr) {
    asm volatile("ldmatrix.sync.aligned.m8n8.x4.shared.b16 {%0,%1,%2,%3}, [%4];"
                 : "=r"(r[0]), "=r"(r[1]), "=r"(r[2]), "=r"(r[3]) : "r"(addr));
}
__device__ __forceinline__ void ldsm4t(uint32_t* r, uint32_t addr) {
    asm volatile("ldmatrix.sync.aligned.m8n8.x4.trans.shared.b16 {%0,%1,%2,%3}, [%4];"
                 : "=r"(r[0]), "=r"(r[1]), "=r"(r[2]), "=r"(r[3]) : "r"(addr));
}
__device__ __forceinline__ void mma16816(float* d, const uint32_t* a,
                                         uint32_t b0, uint32_t b1) {
    asm volatile("mma.sync.aligned.m16n8k16.row.col.f32.bf16.bf16.f32 "
                 "{%0,%1,%2,%3}, {%4,%5,%6,%7}, {%8,%9}, {%0,%1,%2,%3};"
                 : "+f"(d[0]), "+f"(d[1]), "+f"(d[2]), "+f"(d[3])
                 : "r"(a[0]), "r"(a[1]), "r"(a[2]), "r"(a[3]), "r"(b0), "r"(b1));
}

__global__ __launch_bounds__(THREADS)
void dyn_reward_hmma_kernel(const float* __restrict__ s, const float* __restrict__ a,
                            const float* __restrict__ W1, const float* __restrict__ b1,
                            const float* __restrict__ W2, const float* __restrict__ b2,
                            const float* __restrict__ W3, const float* __restrict__ b3,
                            float* __restrict__ out, int B, int ntile) {
    extern __shared__ char sm[];
    const uint32_t smbase = smem_u32(sm);

    float* smallf = (float*)(sm + SMALL_OFF);
    float* sW1   = smallf;           // 640
    float* sb1   = sW1 + 640;        // 128
    float* sb2   = sb1 + 128;        // 128
    float* sW3T  = sb2 + 128;        // 384 : sW3T[t*128+j] = W3[j][t]
    float* sb3   = sW3T + 384;       // 4
    float* spart = sb3 + 4;          // 192 : partial layer3 sums, col-half 1

    const int tid = threadIdx.x;
    const int w = tid >> 5, lane = tid & 31;
    const int rg = w & 1;            // row group (32 rows)
    const int ch = w >> 1;           // column half (64 cols)
    const int bid = blockIdx.x;

    // ---------------- one-time staging ----------------
    for (int i = tid; i < 640; i += THREADS) sW1[i] = W1[i];
    for (int i = tid; i < 384; i += THREADS) {
        int tt = i >> 7, j = i & 127;
        sW3T[i] = W3[j * 3 + tt];
    }
    if (tid < 128) { sb1[tid] = b1[tid]; sb2[tid] = b2[tid]; }
    if (tid < 3)   { sb3[tid] = b3[tid]; }
    {
        __nv_bfloat16* w2h = (__nv_bfloat16*)(sm + W2HI_OFF);
        __nv_bfloat16* w2l = (__nv_bfloat16*)(sm + W2LO_OFF);
        for (int idx = tid; idx < 16384; idx += THREADS) {
            int k = idx >> 7, n = idx & 127;
            float wv = W2[idx];
            __nv_bfloat16 hi = __float2bfloat16_rn(wv);
            __nv_bfloat16 lo = __float2bfloat16_rn(wv - __bfloat162float(hi));
            w2h[k * STRIDE_E + n] = hi;
            w2l[k * STRIDE_E + n] = lo;
        }
    }
    __syncthreads();

    // ldmatrix lane-address offsets; two 16-row subtiles per warp
    const uint32_t a_off0 = (uint32_t)((rg * 32 +      (lane & 15)) * STRIDE_B + ((lane >> 4) << 4));
    const uint32_t a_off1 = (uint32_t)((rg * 32 + 16 + (lane & 15)) * STRIDE_B + ((lane >> 4) << 4));
    const uint32_t b_off  = (uint32_t)((lane & 15) * STRIDE_B + ((lane >> 4) << 4) + ch * 128);

    // -------- one-time: cache ALL Bhi fragments in registers (128 regs) -----
    uint32_t bhi[8][4][4];
    {
        const uint32_t BbHi = smbase + W2HI_OFF + b_off;
        #pragma unroll
        for (int ks = 0; ks < 8; ++ks)
            #pragma unroll
            for (int p = 0; p < 4; ++p)
                ldsm4t(bhi[ks][p], BbHi + (uint32_t)(ks * 16 * STRIDE_B + p * 32));
    }

    const int nt = (ntile - bid + GRID - 1) / GRID;

    for (int it = 0; it < nt; ++it) {
        const int R0 = (bid + it * GRID) * TILE;

        // ---------------- layer 1: h1 = relu(xW1+b1), split hi/lo -------
        {
            const int row = tid & 63;
            const int half = tid >> 6;         // 0..1 -> 64 features each
            const int R = R0 + row;
            const float x0 = s[(size_t)R * 3 + 0];
            const float x1 = s[(size_t)R * 3 + 1];
            const float x2 = s[(size_t)R * 3 + 2];
            const float x3 = a[(size_t)R * 2 + 0];
            const float x4 = a[(size_t)R * 2 + 1];
            char* hiP = sm + H1HI_OFF;
            char* loP = sm + H1LO_OFF;
            #pragma unroll
            for (int g = 0; g < 8; ++g) {
                const int j = half * 64 + g * 8;
                float v[8];
                #pragma unroll
                for (int u = 0; u < 8; u += 4) {
                    float4 wb = *(const float4*)(sb1 + j + u);
                    float4 w0 = *(const float4*)(sW1 + 0 * 128 + j + u);
                    float4 w1 = *(const float4*)(sW1 + 1 * 128 + j + u);
                    float4 w2 = *(const float4*)(sW1 + 2 * 128 + j + u);
                    float4 w3 = *(const float4*)(sW1 + 3 * 128 + j + u);
                    float4 w4 = *(const float4*)(sW1 + 4 * 128 + j + u);
                    v[u+0] = fmaxf(wb.x + x0*w0.x + x1*w1.x + x2*w2.x + x3*w3.x + x4*w4.x, 0.0f);
                    v[u+1] = fmaxf(wb.y + x0*w0.y + x1*w1.y + x2*w2.y + x3*w3.y + x4*w4.y, 0.0f);
                    v[u+2] = fmaxf(wb.z + x0*w0.z + x1*w1.z + x2*w2.z + x3*w3.z + x4*w4.z, 0.0f);
                    v[u+3] = fmaxf(wb.w + x0*w0.w + x1*w1.w + x2*w2.w + x3*w3.w + x4*w4.w, 0.0f);
                }
                uint32_t hw[4], lw[4];
                #pragma unroll
                for (int u = 0; u < 8; u += 2) {
                    // packed bf16x2 hi/lo split (same RN rounding as scalar path)
                    float2 vv = make_float2(v[u], v[u+1]);
                    __nv_bfloat162 hp = __float22bfloat162_rn(vv);
                    float2 hf = __bfloat1622float2(hp);
                    float2 rv = make_float2(vv.x - hf.x, vv.y - hf.y);
                    __nv_bfloat162 lp = __float22bfloat162_rn(rv);
                    hw[u>>1] = *reinterpret_cast<uint32_t*>(&hp);
                    lw[u>>1] = *reinterpret_cast<uint32_t*>(&lp);
                }
                const uint32_t off = (uint32_t)(row * STRIDE_B + j * 2);
                *reinterpret_cast<uint4*>(hiP + off) = make_uint4(hw[0], hw[1], hw[2], hw[3]);
                *reinterpret_cast<uint4*>(loP + off) = make_uint4(lw[0], lw[1], lw[2], lw[3]);
            }
        }
        __syncthreads();

        // ------- layer 2: 3-pass bf16x3 HMMA, warp = 32 rows x 64 cols --
        // (byte-identical structure to the R10 kernel — do not perturb)
        float acc0[32], acc1[32];
        #pragma unroll
        for (int z = 0; z < 32; ++z) { acc0[z] = 0.0f; acc1[z] = 0.0f; }

        // pass 0: Ahi * Bhi  (B from registers)
        {
            const uint32_t Ab0 = smbase + H1HI_OFF + a_off0;
            const uint32_t Ab1 = smbase + H1HI_OFF + a_off1;
            #pragma unroll
            for (int ks = 0; ks < 8; ++ks) {
                uint32_t af0[4], af1[4];
                ldsm4(af0, Ab0 + ks * 32);
                ldsm4(af1, Ab1 + ks * 32);
                #pragma unroll
                for (int p = 0; p < 4; ++p) {
                    mma16816(acc0 + (p * 2 + 0) * 4, af0, bhi[ks][p][0], bhi[ks][p][1]);
                    mma16816(acc0 + (p * 2 + 1) * 4, af0, bhi[ks][p][2], bhi[ks][p][3]);
                    mma16816(acc1 + (p * 2 + 0) * 4, af1, bhi[ks][p][0], bhi[ks][p][1]);
                    mma16816(acc1 + (p * 2 + 1) * 4, af1, bhi[ks][p][2], bhi[ks][p][3]);
                }
            }
        }
        // pass 1: Ahi * Blo  (B from SMEM)
        {
            const uint32_t Ab0 = smbase + H1HI_OFF + a_off0;
            const uint32_t Ab1 = smbase + H1HI_OFF + a_off1;
            const uint32_t Bb  = smbase + W2LO_OFF + b_off;
            #pragma unroll
            for (int ks = 0; ks < 8; ++ks) {
                uint32_t af0[4], af1[4], bfr[4][4];
                ldsm4(af0, Ab0 + ks * 32);
                ldsm4(af1, Ab1 + ks * 32);
                #pragma unroll
                for (int p = 0; p < 4; ++p)
                    ldsm4t(bfr[p], Bb + (uint32_t)(ks * 16 * STRIDE_B + p * 32));
                #pragma unroll
                for (int p = 0; p < 4; ++p) {
                    mma16816(acc0 + (p * 2 + 0) * 4, af0, bfr[p][0], bfr[p][1]);
                    mma16816(acc0 + (p * 2 + 1) * 4, af0, bfr[p][2], bfr[p][3]);
                    mma16816(acc1 + (p * 2 + 0) * 4, af1, bfr[p][0], bfr[p][1]);
                    mma16816(acc1 + (p * 2 + 1) * 4, af1, bfr[p][2], bfr[p][3]);
                }
            }
        }
        // pass 2: Alo * Bhi  (B from registers)
        {
            const uint32_t Ab0 = smbase + H1LO_OFF + a_off0;
            const uint32_t Ab1 = smbase + H1LO_OFF + a_off1;
            #pragma unroll
            for (int ks = 0; ks < 8; ++ks) {
                uint32_t af0[4], af1[4];
                ldsm4(af0, Ab0 + ks * 32);
                ldsm4(af1, Ab1 + ks * 32);
                #pragma unroll
                for (int p = 0; p < 4; ++p) {
                    mma16816(acc0 + (p * 2 + 0) * 4, af0, bhi[ks][p][0], bhi[ks][p][1]);
                    mma16816(acc0 + (p * 2 + 1) * 4, af0, bhi[ks][p][2], bhi[ks][p][3]);
                    mma16816(acc1 + (p * 2 + 0) * 4, af1, bhi[ks][p][0], bhi[ks][p][1]);
                    mma16816(acc1 + (p * 2 + 1) * 4, af1, bhi[ks][p][2], bhi[ks][p][3]);
                }
            }
        }

        // ------- layer 3 partials over this warp's 64 cols (4 rows/lane)
        float po[4][3];
        #pragma unroll
        for (int z = 0; z < 4; ++z) po[z][0] = po[z][1] = po[z][2] = 0.0f;

        #pragma unroll
        for (int t = 0; t < 2; ++t) {
            const float* acc = t ? acc1 : acc0;
            #pragma unroll
            for (int ntl = 0; ntl < 8; ++ntl) {
                const int c0 = ch * 64 + ntl * 8 + (lane & 3) * 2;
                const float2 b2v = *(const float2*)(sb2 + c0);
                const float2 wav = *(const float2*)(sW3T + c0);
                const float2 wbv = *(const float2*)(sW3T + 128 + c0);
                const float2 wcv = *(const float2*)(sW3T + 256 + c0);
                const float h00 = fmaxf(acc[ntl*4+0] + b2v.x, 0.0f);
                const float h01 = fmaxf(acc[ntl*4+1] + b2v.y, 0.0f);
                const float h10 = fmaxf(acc[ntl*4+2] + b2v.x, 0.0f);
                const float h11 = fmaxf(acc[ntl*4+3] + b2v.y, 0.0f);
                po[t*2+0][0] = fmaf(h00, wav.x, fmaf(h01, wav.y, po[t*2+0][0]));
                po[t*2+0][1] = fmaf(h00, wbv.x, fmaf(h01, wbv.y, po[t*2+0][1]));
                po[t*2+0][2] = fmaf(h00, wcv.x, fmaf(h01, wcv.y, po[t*2+0][2]));
                po[t*2+1][0] = fmaf(h10, wav.x, fmaf(h11, wav.y, po[t*2+1][0]));
                po[t*2+1][1] = fmaf(h10, wbv.x, fmaf(h11, wbv.y, po[t*2+1][1]));
                po[t*2+1][2] = fmaf(h10, wcv.x, fmaf(h11, wcv.y, po[t*2+1][2]));
            }
        }
        #pragma unroll
        for (int d = 1; d < 4; d <<= 1) {
            #pragma unroll
            for (int z = 0; z < 4; ++z) {
                po[z][0] += __shfl_xor_sync(0xFFFFFFFFu, po[z][0], d);
                po[z][1] += __shfl_xor_sync(0xFFFFFFFFu, po[z][1], d);
                po[z][2] += __shfl_xor_sync(0xFFFFFFFFu, po[z][2], d);
            }
        }
        // rows for z = t*2+rr : rg*32 + t*16 + rr*8 + (lane>>2)
        if (ch == 1 && (lane & 3) == 0) {
            #pragma unroll
            for (int z = 0; z < 4; ++z) {
                const int lr = rg * 32 + (z >> 1) * 16 + (z & 1) * 8 + (lane >> 2);
                spart[lr * 3 + 0] = po[z][0];
                spart[lr * 3 + 1] = po[z][1];
                spart[lr * 3 + 2] = po[z][2];
            }
        }
        __syncthreads();    // spart ready AND h1 LDSM complete (reusable next tile)

        if (ch == 0 && (lane & 3) == 0) {
            #pragma unroll
            for (int z = 0; z < 4; ++z) {
                const int lr = rg * 32 + (z >> 1) * 16 + (z & 1) * 8 + (lane >> 2);
                const int R = R0 + lr;
                out[(size_t)R * 3 + 0] = po[z][0] + spart[lr * 3 + 0] + sb3[0];
                out[(size_t)R * 3 + 1] = po[z][1] + spart[lr * 3 + 1] + sb3[1];
                out[(size_t)R * 3 + 2] = po[z][2] + spart[lr * 3 + 2] + sb3[2];
            }
        }
        // ---- reward: ALL 4 warps, 16 rows each (lanes 0-15), balanced tail ----
        if (lane < 16) {
            const int R = R0 + w * 16 + lane;
            const float x0 = s[(size_t)R * 3 + 0];
            const float x1 = s[(size_t)R * 3 + 1];
            const float x3 = a[(size_t)R * 2 + 0];
            const float x4 = a[(size_t)R * 2 + 1];
            const float INV2VAR = 14.2857142857f;
            const float GC      = 454.728409f;
            const float BEXP    = 555.5555556f;
            const float BC      = 132.9807601f;
            float g = 0.0f, dx, dy, t;
            dx = x0;        dy = x1;        g += __expf(-(dx*dx + dy*dy) * INV2VAR);
            dx = x0;        dy = x1 - 0.2f; g += __expf(-(dx*dx + dy*dy) * INV2VAR);
            dx = x0;        dy = x1 - 0.4f; g += __expf(-(dx*dx + dy*dy) * INV2VAR);
            dx = x0;        dy = x1 - 0.6f; g += __expf(-(dx*dx + dy*dy) * INV2VAR);
            dx = x0;        dy = x1 - 0.8f; g += __expf(-(dx*dx + dy*dy) * INV2VAR);
            dx = x0 + 0.8f; dy = x1 + 0.8f; g += __expf(-(dx*dx + dy*dy) * INV2VAR);
            const float dq0 = x0 - x3, dq1 = x1 - x4;
            const float quad = 30.0f * (dq0 * dq0 + dq1 * dq1);
            float bs = 0.0f;
            t = x0 + 1.5f; bs += __expf(-t * t * BEXP);
            t = x0 - 1.5f; bs += __expf(-t * t * BEXP);
            t = x1 - 1.0f; bs += __expf(-t * t * BEXP);
            t = x1 + 1.0f; bs += __expf(-t * t * BEXP);
            out[(size_t)B * 3 + R] = -(quad + GC * g + BC * bs);
        }
    }
}

extern "C" void kernel_launch(void* const* d_in, const int* in_sizes, int n_in,
                              void* d_out, int out_size) {
    const float* s  = (const float*)d_in[0];
    const float* a  = (const float*)d_in[1];
    const float* W1 = (const float*)d_in[2];
    const float* b1 = (const float*)d_in[3];
    const float* W2 = (const float*)d_in[4];
    const float* b2 = (const float*)d_in[5];
    const float* W3 = (const float*)d_in[6];
    const float* b3 = (const float*)d_in[7];
    float* out = (float*)d_out;

    const int B = in_sizes[0] / 3;
    const int ntile = B / TILE;       // 8192
    cudaFuncSetAttribute(dyn_reward_hmma_kernel,
                         cudaFuncAttributeMaxDynamicSharedMemorySize, SMEM_TOTAL);
    const int grid = (ntile < GRID) ? ntile : GRID;
    dyn_reward_hmma_kernel<<<grid, THREADS, SMEM_TOTAL>>>(s, a, W1, b1, W2, b2, W3, b3,
                                                          out, B, ntile);
}